// round 1
// baseline (speedup 1.0000x reference)
#include <cuda_runtime.h>
#include <cuda_bf16.h>
#include <stdint.h>
#include <math.h>

// Problem dims
#define B_   65536
#define D_   1024
#define E_   16
#define H1_  128
#define H2_  64
#define R1_  64
#define R2_  32
#define NCAT 2112   // 64 router + 16*128 expert cols
#define NP   2176   // padded to 17*128
#define EPS  1e-5f

// ---------------- device scratch (no allocs allowed) ----------------
__device__ __nv_bfloat16 g_xb[(size_t)B_ * D_];           // x in bf16
__device__ __nv_bfloat16 g_Wt[(size_t)NP * D_];           // folded W1, [n][k]
__device__ float         g_bcat[NP];                      // folded bias
__device__ __nv_bfloat16 g_C1[(size_t)B_ * NP];           // relu(x@W1+b), bf16
__device__ __nv_bfloat16 g_W2t[(size_t)E_ * H2_ * H1_];   // eW2 transposed [e][n][k]
__device__ __nv_bfloat16 g_Hs[(size_t)B_ * E_ * H2_];     // relu(h1@W2+b2)

// ---------------- mma helper ----------------
__device__ __forceinline__ void mma16816(float c[4],
    uint32_t a0, uint32_t a1, uint32_t a2, uint32_t a3,
    uint32_t b0, uint32_t b1) {
  asm volatile(
    "mma.sync.aligned.m16n8k16.row.col.f32.bf16.bf16.f32 "
    "{%0,%1,%2,%3},{%4,%5,%6,%7},{%8,%9},{%0,%1,%2,%3};"
    : "+f"(c[0]), "+f"(c[1]), "+f"(c[2]), "+f"(c[3])
    : "r"(a0), "r"(a1), "r"(a2), "r"(a3), "r"(b0), "r"(b1));
}

// ---------------- P: convert x fp32 -> bf16 ----------------
__global__ __launch_bounds__(256) void k_cvtx(const float* __restrict__ x) {
  size_t i = (size_t)blockIdx.x * 256 + threadIdx.x;   // one float4 per thread
  float4 v = ((const float4*)x)[i];
  __nv_bfloat162* o = (__nv_bfloat162*)g_xb;
  o[2 * i]     = __floats2bfloat162_rn(v.x, v.y);
  o[2 * i + 1] = __floats2bfloat162_rn(v.z, v.w);
}

// ---------------- P: fold BN into W1 (router + experts), compute bias ----
__global__ __launch_bounds__(256) void k_fold(
    const float* __restrict__ rg, const float* __restrict__ rb,
    const float* __restrict__ rm, const float* __restrict__ rv,
    const float* __restrict__ rW1, const float* __restrict__ rb1,
    const float* __restrict__ eg, const float* __restrict__ ebt,
    const float* __restrict__ em, const float* __restrict__ ev,
    const float* __restrict__ eW1, const float* __restrict__ eb1) {
  int n = blockIdx.x;
  int tid = threadIdx.x;
  __shared__ float red[256];
  float acc = 0.f;
  if (n < R1_) {
    for (int k = tid; k < D_; k += 256) {
      float sc = rg[k] * rsqrtf(rv[k] + EPS);
      float sh = rb[k] - rm[k] * sc;
      float wv = rW1[(size_t)k * R1_ + n];
      g_Wt[(size_t)n * D_ + k] = __float2bfloat16(wv * sc);
      acc += sh * wv;
    }
  } else if (n < NCAT) {
    int e = (n - R1_) >> 7, h = (n - R1_) & 127;
    const float* W = eW1 + (size_t)e * D_ * H1_;
    const float* Gg = eg + (size_t)e * D_;
    const float* Gb = ebt + (size_t)e * D_;
    const float* Gm = em + (size_t)e * D_;
    const float* Gv = ev + (size_t)e * D_;
    for (int k = tid; k < D_; k += 256) {
      float sc = Gg[k] * rsqrtf(Gv[k] + EPS);
      float sh = Gb[k] - Gm[k] * sc;
      float wv = W[(size_t)k * H1_ + h];
      g_Wt[(size_t)n * D_ + k] = __float2bfloat16(wv * sc);
      acc += sh * wv;
    }
  } else {
    for (int k = tid; k < D_; k += 256)
      g_Wt[(size_t)n * D_ + k] = __float2bfloat16(0.f);
  }
  red[tid] = acc;
  __syncthreads();
  for (int s = 128; s > 0; s >>= 1) {
    if (tid < s) red[tid] += red[tid + s];
    __syncthreads();
  }
  if (tid == 0) {
    float base = 0.f;
    if (n < R1_) base = rb1[n];
    else if (n < NCAT) base = eb1[(size_t)((n - R1_) >> 7) * H1_ + ((n - R1_) & 127)];
    g_bcat[n] = base + red[0];
  }
}

// ---------------- P: transpose+convert eW2 -> [e][h2][h1] bf16 ----------
__global__ __launch_bounds__(256) void k_w2t(const float* __restrict__ eW2) {
  int idx = blockIdx.x * 256 + threadIdx.x;  // < 16*128*64 = 131072
  int e = idx >> 13;
  int r = idx & 8191;
  int k = r >> 6;   // h1
  int n = r & 63;   // h2
  g_W2t[((size_t)e * H2_ + n) * H1_ + k] = __float2bfloat16(eW2[idx]);
}

// ---------------- GEMM1: C1 = relu(xb @ Wt^T + bcat)  [B x NP] -----------
// BM=128, BN=128, BK=32, 256 thr (8 warps, 2m x 4n), warp tile 64x32
__global__ __launch_bounds__(256) void k_gemm1() {
  const int n0 = blockIdx.x * 128;
  const int m0 = blockIdx.y * 128;
  __shared__ __nv_bfloat16 As[128][40];
  __shared__ __nv_bfloat16 Bs[128][40];
  const int tid = threadIdx.x;
  const int wid = tid >> 5, lane = tid & 31;
  const int g = lane >> 2, t = lane & 3;
  const int mW = wid >> 2, nW = wid & 3;

  float acc[4][4][4];
#pragma unroll
  for (int i = 0; i < 4; i++)
#pragma unroll
    for (int j = 0; j < 4; j++)
#pragma unroll
      for (int c = 0; c < 4; c++) acc[i][j][c] = 0.f;

  for (int k0 = 0; k0 < D_; k0 += 32) {
    __syncthreads();
#pragma unroll
    for (int r = 0; r < 2; r++) {
      int u = tid + 256 * r;
      int row = u >> 2, c8 = (u & 3) << 3;
      *(uint4*)&As[row][c8] = *(const uint4*)(g_xb + (size_t)(m0 + row) * D_ + k0 + c8);
      *(uint4*)&Bs[row][c8] = *(const uint4*)(g_Wt + (size_t)(n0 + row) * D_ + k0 + c8);
    }
    __syncthreads();
#pragma unroll
    for (int kk = 0; kk < 32; kk += 16) {
      uint32_t af[4][4], bf[4][2];
#pragma unroll
      for (int i = 0; i < 4; i++) {
        int r = mW * 64 + i * 16 + g;
        af[i][0] = *(const uint32_t*)&As[r][kk + 2 * t];
        af[i][1] = *(const uint32_t*)&As[r + 8][kk + 2 * t];
        af[i][2] = *(const uint32_t*)&As[r][kk + 2 * t + 8];
        af[i][3] = *(const uint32_t*)&As[r + 8][kk + 2 * t + 8];
      }
#pragma unroll
      for (int j = 0; j < 4; j++) {
        int c = nW * 32 + j * 8 + g;
        bf[j][0] = *(const uint32_t*)&Bs[c][kk + 2 * t];
        bf[j][1] = *(const uint32_t*)&Bs[c][kk + 2 * t + 8];
      }
#pragma unroll
      for (int i = 0; i < 4; i++)
#pragma unroll
        for (int j = 0; j < 4; j++)
          mma16816(acc[i][j], af[i][0], af[i][1], af[i][2], af[i][3],
                   bf[j][0], bf[j][1]);
    }
  }
  // epilogue: +bias, relu, bf16 store
#pragma unroll
  for (int i = 0; i < 4; i++) {
#pragma unroll
    for (int j = 0; j < 4; j++) {
      int row = m0 + mW * 64 + i * 16 + g;
      int col = n0 + nW * 32 + j * 8 + 2 * t;
      float b0v = g_bcat[col], b1v = g_bcat[col + 1];
      float f0 = fmaxf(acc[i][j][0] + b0v, 0.f);
      float f1 = fmaxf(acc[i][j][1] + b1v, 0.f);
      float f2 = fmaxf(acc[i][j][2] + b0v, 0.f);
      float f3 = fmaxf(acc[i][j][3] + b1v, 0.f);
      *(__nv_bfloat162*)&g_C1[(size_t)row * NP + col] = __floats2bfloat162_rn(f0, f1);
      *(__nv_bfloat162*)&g_C1[(size_t)(row + 8) * NP + col] = __floats2bfloat162_rn(f2, f3);
    }
  }
}

// ---------------- GEMM2: Hs[e] = relu(C1[:,64+128e:..] @ W2t[e]^T + eb2) --
// BM=128, BN=64, BK=32, 256 thr (8 warps, 4m x 2n), warp tile 32x32
__global__ __launch_bounds__(256) void k_gemm2(const float* __restrict__ eb2) {
  const int m0 = blockIdx.x * 128;
  const int e = blockIdx.y;
  __shared__ __nv_bfloat16 As[128][40];
  __shared__ __nv_bfloat16 Bs[64][40];
  const int tid = threadIdx.x;
  const int wid = tid >> 5, lane = tid & 31;
  const int g = lane >> 2, t = lane & 3;
  const int mW = wid >> 1, nW = wid & 1;
  const size_t abase = R1_ + (size_t)e * 128;

  float acc[2][4][4];
#pragma unroll
  for (int i = 0; i < 2; i++)
#pragma unroll
    for (int j = 0; j < 4; j++)
#pragma unroll
      for (int c = 0; c < 4; c++) acc[i][j][c] = 0.f;

  for (int k0 = 0; k0 < H1_; k0 += 32) {
    __syncthreads();
#pragma unroll
    for (int r = 0; r < 2; r++) {
      int u = tid + 256 * r;
      int row = u >> 2, c8 = (u & 3) << 3;
      *(uint4*)&As[row][c8] =
          *(const uint4*)(g_C1 + (size_t)(m0 + row) * NP + abase + k0 + c8);
    }
    {
      int row = tid >> 2, c8 = (tid & 3) << 3;  // 64 rows * 4 uint4 = 256
      *(uint4*)&Bs[row][c8] =
          *(const uint4*)(g_W2t + ((size_t)e * H2_ + row) * H1_ + k0 + c8);
    }
    __syncthreads();
#pragma unroll
    for (int kk = 0; kk < 32; kk += 16) {
      uint32_t af[2][4], bf[4][2];
#pragma unroll
      for (int i = 0; i < 2; i++) {
        int r = mW * 32 + i * 16 + g;
        af[i][0] = *(const uint32_t*)&As[r][kk + 2 * t];
        af[i][1] = *(const uint32_t*)&As[r + 8][kk + 2 * t];
        af[i][2] = *(const uint32_t*)&As[r][kk + 2 * t + 8];
        af[i][3] = *(const uint32_t*)&As[r + 8][kk + 2 * t + 8];
      }
#pragma unroll
      for (int j = 0; j < 4; j++) {
        int c = nW * 32 + j * 8 + g;
        bf[j][0] = *(const uint32_t*)&Bs[c][kk + 2 * t];
        bf[j][1] = *(const uint32_t*)&Bs[c][kk + 2 * t + 8];
      }
#pragma unroll
      for (int i = 0; i < 2; i++)
#pragma unroll
        for (int j = 0; j < 4; j++)
          mma16816(acc[i][j], af[i][0], af[i][1], af[i][2], af[i][3],
                   bf[j][0], bf[j][1]);
    }
  }
#pragma unroll
  for (int i = 0; i < 2; i++) {
#pragma unroll
    for (int j = 0; j < 4; j++) {
      int row = m0 + mW * 32 + i * 16 + g;
      int col = nW * 32 + j * 8 + 2 * t;
      float b0v = eb2[e * H2_ + col], b1v = eb2[e * H2_ + col + 1];
      float f0 = fmaxf(acc[i][j][0] + b0v, 0.f);
      float f1 = fmaxf(acc[i][j][1] + b1v, 0.f);
      float f2 = fmaxf(acc[i][j][2] + b0v, 0.f);
      float f3 = fmaxf(acc[i][j][3] + b1v, 0.f);
      *(__nv_bfloat162*)&g_Hs[((size_t)row * E_ + e) * H2_ + col] =
          __floats2bfloat162_rn(f0, f1);
      *(__nv_bfloat162*)&g_Hs[((size_t)(row + 8) * E_ + e) * H2_ + col] =
          __floats2bfloat162_rn(f2, f3);
    }
  }
}

// ---------------- Final: router MLP tail + softmax + expert L3 + mix -----
__global__ __launch_bounds__(256) void k_final(
    const float* __restrict__ rW2, const float* __restrict__ rb2,
    const float* __restrict__ rW3, const float* __restrict__ rb3,
    const float* __restrict__ eW3, const float* __restrict__ eb3,
    float* __restrict__ out) {
  __shared__ float s_rW2[R1_ * R2_];
  __shared__ float s_rW3[R2_ * E_];
  __shared__ float s_eW3[E_ * H2_];
  __shared__ float s_rb2[R2_], s_rb3[E_], s_eb3[E_];
  __shared__ float s_h[8][R1_];
  int tid = threadIdx.x;
  for (int i = tid; i < R1_ * R2_; i += 256) s_rW2[i] = rW2[i];
  for (int i = tid; i < R2_ * E_; i += 256) s_rW3[i] = rW3[i];
  for (int i = tid; i < E_ * H2_; i += 256) s_eW3[i] = eW3[i];
  if (tid < R2_) s_rb2[tid] = rb2[tid];
  if (tid < E_) { s_rb3[tid] = rb3[tid]; s_eb3[tid] = eb3[tid]; }
  __syncthreads();

  int w = tid >> 5, lane = tid & 31;
  int b = blockIdx.x * 8 + w;

  // router hidden h (already ReLU'd, bf16 in C1 cols [0,64))
  const __nv_bfloat162* hp = (const __nv_bfloat162*)(g_C1 + (size_t)b * NP);
  __nv_bfloat162 hv = hp[lane];
  s_h[w][2 * lane] = __bfloat162float(hv.x);
  s_h[w][2 * lane + 1] = __bfloat162float(hv.y);
  __syncwarp();

  // layer2: lane n computes d1[n]
  float d1 = s_rb2[lane];
#pragma unroll
  for (int k = 0; k < R1_; k++) d1 += s_h[w][k] * s_rW2[k * R2_ + lane];
  d1 = fmaxf(d1, 0.f);

  // layer3: lanes 0..15 compute logits
  float d2 = (lane < E_) ? s_rb3[lane] : 0.f;
#pragma unroll
  for (int k = 0; k < R2_; k++) {
    float v = __shfl_sync(0xffffffffu, d1, k);
    if (lane < E_) d2 += v * s_rW3[k * E_ + lane];
  }
  // softmax over 16 lanes
  float m = d2;
#pragma unroll
  for (int off = 8; off > 0; off >>= 1)
    m = fmaxf(m, __shfl_xor_sync(0xffffffffu, m, off, 16));
  float ex = __expf(d2 - m);
  float s = ex;
#pragma unroll
  for (int off = 8; off > 0; off >>= 1)
    s += __shfl_xor_sync(0xffffffffu, s, off, 16);
  float rw = ex / s;

  // expert L3: lane e does dot-64 over Hs
  float eo = 0.f;
  if (lane < E_) {
    float a2 = s_eb3[lane];
    const __nv_bfloat162* q =
        (const __nv_bfloat162*)(g_Hs + ((size_t)b * E_ + lane) * H2_);
#pragma unroll
    for (int n = 0; n < H2_ / 2; n++) {
      __nv_bfloat162 v = q[n];
      a2 += __bfloat162float(v.x) * s_eW3[lane * H2_ + 2 * n] +
            __bfloat162float(v.y) * s_eW3[lane * H2_ + 2 * n + 1];
    }
    eo = 1.f / (1.f + __expf(-a2));
  }
  float p = rw * eo;
#pragma unroll
  for (int off = 8; off > 0; off >>= 1)
    p += __shfl_xor_sync(0xffffffffu, p, off, 16);

  if (lane < E_) {
    out[(size_t)B_ + (size_t)b * E_ + lane] = rw;                      // routing_weights
    out[(size_t)B_ + (size_t)B_ * E_ + (size_t)b * E_ + lane] = eo;    // expert_outputs
  }
  if (lane == 0) out[b] = p;                                           // weighted_pred
}

// ---------------- launch ----------------
extern "C" void kernel_launch(void* const* d_in, const int* in_sizes, int n_in,
                              void* d_out, int out_size) {
  const float* x     = (const float*)d_in[0];
  const float* rg    = (const float*)d_in[1];
  const float* rbta  = (const float*)d_in[2];
  const float* rm    = (const float*)d_in[3];
  const float* rv    = (const float*)d_in[4];
  const float* rW1   = (const float*)d_in[5];
  const float* rb1   = (const float*)d_in[6];
  const float* rW2   = (const float*)d_in[7];
  const float* rb2   = (const float*)d_in[8];
  const float* rW3   = (const float*)d_in[9];
  const float* rb3   = (const float*)d_in[10];
  const float* eg    = (const float*)d_in[11];
  const float* ebt   = (const float*)d_in[12];
  const float* em    = (const float*)d_in[13];
  const float* ev    = (const float*)d_in[14];
  const float* eW1   = (const float*)d_in[15];
  const float* eb1   = (const float*)d_in[16];
  const float* eW2   = (const float*)d_in[17];
  const float* eb2   = (const float*)d_in[18];
  const float* eW3   = (const float*)d_in[19];
  const float* eb3   = (const float*)d_in[20];
  float* out = (float*)d_out;

  k_cvtx<<<(B_ * D_ / 4) / 256, 256>>>(x);
  k_fold<<<NP, 256>>>(rg, rbta, rm, rv, rW1, rb1, eg, ebt, em, ev, eW1, eb1);
  k_w2t<<<(E_ * H1_ * H2_) / 256, 256>>>(eW2);
  k_gemm1<<<dim3(NP / 128, B_ / 128), 256>>>();
  k_gemm2<<<dim3(B_ / 128, E_), 256>>>(eb2);
  k_final<<<B_ / 8, 256>>>(rW2, rb2, rW3, rb3, eW3, eb3, out);
}

// round 2
// speedup vs baseline: 1.4994x; 1.4994x over previous
#include <cuda_runtime.h>
#include <cuda_bf16.h>
#include <stdint.h>
#include <math.h>

// Problem dims
#define B_   65536
#define D_   1024
#define E_   16
#define H1_  128
#define H2_  64
#define R1_  64
#define R2_  32
// Column layout of the big GEMM: [16*128 expert cols][64 router cols][64 pad] = 2176
#define NEXP (E_ * H1_)          // 2048
#define NCAT (NEXP + R1_)        // 2112
#define NP   2176
#define EPS  1e-5f

// ---------------- device scratch (no allocs allowed) ----------------
__device__ __nv_bfloat16 g_xb[(size_t)B_ * D_];           // x in bf16
__device__ __nv_bfloat16 g_Wt[(size_t)NP * D_];           // folded W1, [n][k]
__device__ float         g_bcat[NP];                      // folded bias
__device__ __nv_bfloat16 g_Cr[(size_t)B_ * R1_];          // router hidden (relu), bf16
__device__ __nv_bfloat16 g_W2t[(size_t)E_ * H2_ * H1_];   // eW2 transposed [e][h2][h1]
__device__ __nv_bfloat16 g_Hs[(size_t)B_ * E_ * H2_];     // relu(h1@W2+b2)

// ---------------- asm helpers ----------------
__device__ __forceinline__ void mma16816(float c[4],
    uint32_t a0, uint32_t a1, uint32_t a2, uint32_t a3,
    uint32_t b0, uint32_t b1) {
  asm volatile(
    "mma.sync.aligned.m16n8k16.row.col.f32.bf16.bf16.f32 "
    "{%0,%1,%2,%3},{%4,%5,%6,%7},{%8,%9},{%0,%1,%2,%3};"
    : "+f"(c[0]), "+f"(c[1]), "+f"(c[2]), "+f"(c[3])
    : "r"(a0), "r"(a1), "r"(a2), "r"(a3), "r"(b0), "r"(b1));
}

__device__ __forceinline__ void ldsm4(uint32_t& r0, uint32_t& r1,
                                      uint32_t& r2, uint32_t& r3, uint32_t addr) {
  asm volatile("ldmatrix.sync.aligned.m8n8.x4.shared.b16 {%0,%1,%2,%3},[%4];"
               : "=r"(r0), "=r"(r1), "=r"(r2), "=r"(r3) : "r"(addr));
}

__device__ __forceinline__ void cp_async16(uint32_t saddr, const void* gaddr) {
  asm volatile("cp.async.cg.shared.global [%0],[%1],16;" ::"r"(saddr), "l"(gaddr)
               : "memory");
}
__device__ __forceinline__ void cp_commit() {
  asm volatile("cp.async.commit_group;" ::: "memory");
}
__device__ __forceinline__ void cp_wait1() {
  asm volatile("cp.async.wait_group 1;" ::: "memory");
}

__device__ __forceinline__ uint32_t smem_u32(const void* p) {
  uint32_t a;
  asm("{.reg .u64 t; cvta.to.shared.u64 t, %1; cvt.u32.u64 %0, t;}"
      : "=r"(a) : "l"(p));
  return a;
}

// swizzled byte offsets: tile row of 64 bf16 (128B, 8 chunks) / 128 bf16 (256B, 16 chunks)
__device__ __forceinline__ uint32_t swz64(uint32_t row, uint32_t chunk) {
  return row * 128u + ((chunk ^ (row & 7u)) << 4);
}
__device__ __forceinline__ uint32_t swz128(uint32_t row, uint32_t chunk) {
  return row * 256u + ((chunk ^ (row & 7u)) << 4);
}

// ---------------- P: convert x fp32 -> bf16 ----------------
__global__ __launch_bounds__(256) void k_cvtx(const float* __restrict__ x) {
  size_t i = (size_t)blockIdx.x * 256 + threadIdx.x;
  float4 v = ((const float4*)x)[i];
  __nv_bfloat162* o = (__nv_bfloat162*)g_xb;
  o[2 * i]     = __floats2bfloat162_rn(v.x, v.y);
  o[2 * i + 1] = __floats2bfloat162_rn(v.z, v.w);
}

// ---------------- P: fold BN into W1 (experts first, router, pad) --------
__global__ __launch_bounds__(256) void k_fold(
    const float* __restrict__ rg, const float* __restrict__ rb,
    const float* __restrict__ rm, const float* __restrict__ rv,
    const float* __restrict__ rW1, const float* __restrict__ rb1,
    const float* __restrict__ eg, const float* __restrict__ ebt,
    const float* __restrict__ em, const float* __restrict__ ev,
    const float* __restrict__ eW1, const float* __restrict__ eb1) {
  int n = blockIdx.x;
  int tid = threadIdx.x;
  __shared__ float red[256];
  float acc = 0.f;
  if (n < NEXP) {
    int e = n >> 7, h = n & 127;
    const float* W = eW1 + (size_t)e * D_ * H1_;
    const float* Gg = eg + (size_t)e * D_;
    const float* Gb = ebt + (size_t)e * D_;
    const float* Gm = em + (size_t)e * D_;
    const float* Gv = ev + (size_t)e * D_;
    for (int k = tid; k < D_; k += 256) {
      float sc = Gg[k] * rsqrtf(Gv[k] + EPS);
      float sh = Gb[k] - Gm[k] * sc;
      float wv = W[(size_t)k * H1_ + h];
      g_Wt[(size_t)n * D_ + k] = __float2bfloat16(wv * sc);
      acc += sh * wv;
    }
  } else if (n < NCAT) {
    int rn = n - NEXP;
    for (int k = tid; k < D_; k += 256) {
      float sc = rg[k] * rsqrtf(rv[k] + EPS);
      float sh = rb[k] - rm[k] * sc;
      float wv = rW1[(size_t)k * R1_ + rn];
      g_Wt[(size_t)n * D_ + k] = __float2bfloat16(wv * sc);
      acc += sh * wv;
    }
  } else {
    for (int k = tid; k < D_; k += 256)
      g_Wt[(size_t)n * D_ + k] = __float2bfloat16(0.f);
  }
  red[tid] = acc;
  __syncthreads();
  for (int s = 128; s > 0; s >>= 1) {
    if (tid < s) red[tid] += red[tid + s];
    __syncthreads();
  }
  if (tid == 0) {
    float base = 0.f;
    if (n < NEXP) base = eb1[(size_t)(n >> 7) * H1_ + (n & 127)];
    else if (n < NCAT) base = rb1[n - NEXP];
    g_bcat[n] = base + red[0];
  }
}

// ---------------- P: transpose+convert eW2 -> [e][h2][h1] bf16 ----------
__global__ __launch_bounds__(256) void k_w2t(const float* __restrict__ eW2) {
  int idx = blockIdx.x * 256 + threadIdx.x;  // < 16*128*64
  int e = idx >> 13;
  int r = idx & 8191;
  int k = r >> 6;   // h1
  int n = r & 63;   // h2
  g_W2t[((size_t)e * H2_ + n) * H1_ + k] = __float2bfloat16(eW2[idx]);
}

// ---------------- Fused GEMM1 (+bias+relu) + per-expert GEMM2 ------------
// BM=128, BN=128, BK=64, 3-stage cp.async, ldmatrix, 256 thr (2m x 4n warps)
// Smem: As[3][128][64] @0 (48KB) | Bs[3][128][64] @48K (48KB) | W2s[64][128] @96K (16KB)
// H1s[128][128] reuses As region after mainloop.
#define SM_A   0u
#define SM_B   49152u
#define SM_W2  98304u
#define SM_TOT (98304 + 16384)

__global__ __launch_bounds__(256) void k_gemm1f(const float* __restrict__ eb2) {
  extern __shared__ char smem[];
  const uint32_t sb = smem_u32(smem);
  const int bx = blockIdx.x;            // 0..15 experts, 16 = router(+pad)
  const int m0 = blockIdx.y * 128;
  const int n0 = bx * 128;
  const int tid = threadIdx.x;
  const int wid = tid >> 5, lane = tid & 31;
  const int g = lane >> 2, t = lane & 3;
  const int mW = wid >> 2, nW = wid & 3;
  const int lr = lane & 15, lc = lane >> 4;   // ldmatrix row-in-16 / chunk add

  float acc[4][4][4];
#pragma unroll
  for (int i = 0; i < 4; i++)
#pragma unroll
    for (int j = 0; j < 4; j++)
#pragma unroll
      for (int c = 0; c < 4; c++) acc[i][j][c] = 0.f;

  // stage load: 128x64 A + 128x64 B, 16B per cp.async
  auto load_stage = [&](int st, int k0) {
#pragma unroll
    for (int i = 0; i < 4; i++) {
      int idx = tid + 256 * i;          // 0..1023
      int row = idx >> 3, ch = idx & 7;
      uint32_t so = swz64(row, ch);
      cp_async16(sb + SM_A + st * 16384u + so,
                 g_xb + (size_t)(m0 + row) * D_ + k0 + ch * 8);
      cp_async16(sb + SM_B + st * 16384u + so,
                 g_Wt + (size_t)(n0 + row) * D_ + k0 + ch * 8);
    }
  };

  load_stage(0, 0);  cp_commit();
  load_stage(1, 64); cp_commit();

  const int NITER = D_ / 64;  // 16
  for (int it = 0; it < NITER; ++it) {
    cp_wait1();
    __syncthreads();
    if (it + 2 < NITER) load_stage((it + 2) % 3, (it + 2) * 64);
    cp_commit();
    const uint32_t sAb = sb + SM_A + (uint32_t)(it % 3) * 16384u;
    const uint32_t sBb = sb + SM_B + (uint32_t)(it % 3) * 16384u;
#pragma unroll
    for (int kk = 0; kk < 4; ++kk) {
      uint32_t a[4][4], bfr[2][4];
#pragma unroll
      for (int i = 0; i < 4; i++)
        ldsm4(a[i][0], a[i][1], a[i][2], a[i][3],
              sAb + swz64(mW * 64 + i * 16 + lr, 2 * kk + lc));
#pragma unroll
      for (int jj = 0; jj < 2; jj++)
        ldsm4(bfr[jj][0], bfr[jj][1], bfr[jj][2], bfr[jj][3],
              sBb + swz64(nW * 32 + jj * 16 + lr, 2 * kk + lc));
#pragma unroll
      for (int i = 0; i < 4; i++)
#pragma unroll
        for (int j = 0; j < 4; j++)
          mma16816(acc[i][j], a[i][0], a[i][1], a[i][2], a[i][3],
                   bfr[j >> 1][j & 1], bfr[j >> 1][(j & 1) + 2]);
    }
  }
  __syncthreads();   // mainloop smem now dead

  if (bx < E_) {
    // ---- write h1 = relu(acc+bias) into H1s (As region), swz128 ----
#pragma unroll
    for (int i = 0; i < 4; i++) {
#pragma unroll
      for (int j = 0; j < 4; j++) {
        int row = mW * 64 + i * 16 + g;
        int col = nW * 32 + j * 8 + 2 * t;
        float b0v = g_bcat[n0 + col], b1v = g_bcat[n0 + col + 1];
        __nv_bfloat162 p0 = __floats2bfloat162_rn(fmaxf(acc[i][j][0] + b0v, 0.f),
                                                  fmaxf(acc[i][j][1] + b1v, 0.f));
        __nv_bfloat162 p1 = __floats2bfloat162_rn(fmaxf(acc[i][j][2] + b0v, 0.f),
                                                  fmaxf(acc[i][j][3] + b1v, 0.f));
        *(__nv_bfloat162*)(smem + SM_A + swz128(row, col >> 3) + (col & 7) * 2) = p0;
        *(__nv_bfloat162*)(smem + SM_A + swz128(row + 8, col >> 3) + (col & 7) * 2) = p1;
      }
    }
    // ---- load W2[e] (64x128 bf16) into W2s, swz128 ----
#pragma unroll
    for (int i = 0; i < 4; i++) {
      int idx = tid + 256 * i;          // 0..1023 = 64 rows x 16 chunks
      int row = idx >> 4, ch = idx & 15;
      uint4 v = *(const uint4*)(g_W2t + ((size_t)bx * H2_ + row) * H1_ + ch * 8);
      *(uint4*)(smem + SM_W2 + swz128(row, ch)) = v;
    }
  } else {
    // ---- router block: cols [0,64) are router hidden ----
#pragma unroll
    for (int i = 0; i < 4; i++) {
      if (nW < 2) {
#pragma unroll
        for (int j = 0; j < 4; j++) {
          int row = m0 + mW * 64 + i * 16 + g;
          int col = nW * 32 + j * 8 + 2 * t;
          float b0v = g_bcat[NEXP + col], b1v = g_bcat[NEXP + col + 1];
          *(__nv_bfloat162*)&g_Cr[(size_t)row * R1_ + col] =
              __floats2bfloat162_rn(fmaxf(acc[i][j][0] + b0v, 0.f),
                                    fmaxf(acc[i][j][1] + b1v, 0.f));
          *(__nv_bfloat162*)&g_Cr[(size_t)(row + 8) * R1_ + col] =
              __floats2bfloat162_rn(fmaxf(acc[i][j][2] + b0v, 0.f),
                                    fmaxf(acc[i][j][3] + b1v, 0.f));
        }
      }
    }
  }
  __syncthreads();
  if (bx >= E_) return;

  // ---- GEMM2: Hs[e] = relu(H1s @ W2s^T + eb2[e]);  m128 x n64, K=128 ----
  float acc2[4][2][4];
#pragma unroll
  for (int i = 0; i < 4; i++)
#pragma unroll
    for (int j = 0; j < 2; j++)
#pragma unroll
      for (int c = 0; c < 4; c++) acc2[i][j][c] = 0.f;

#pragma unroll
  for (int ks = 0; ks < 8; ++ks) {    // 8 k16-steps
    uint32_t a[4][4], bfr[4];
#pragma unroll
    for (int i = 0; i < 4; i++)
      ldsm4(a[i][0], a[i][1], a[i][2], a[i][3],
            sb + SM_A + swz128(mW * 64 + i * 16 + lr, 2 * ks + lc));
    ldsm4(bfr[0], bfr[1], bfr[2], bfr[3],
          sb + SM_W2 + swz128(nW * 16 + lr, 2 * ks + lc));
#pragma unroll
    for (int i = 0; i < 4; i++) {
      mma16816(acc2[i][0], a[i][0], a[i][1], a[i][2], a[i][3], bfr[0], bfr[2]);
      mma16816(acc2[i][1], a[i][0], a[i][1], a[i][2], a[i][3], bfr[1], bfr[3]);
    }
  }
#pragma unroll
  for (int i = 0; i < 4; i++) {
#pragma unroll
    for (int j = 0; j < 2; j++) {
      int row = m0 + mW * 64 + i * 16 + g;
      int col = nW * 16 + j * 8 + 2 * t;
      float b0v = eb2[bx * H2_ + col], b1v = eb2[bx * H2_ + col + 1];
      *(__nv_bfloat162*)&g_Hs[((size_t)row * E_ + bx) * H2_ + col] =
          __floats2bfloat162_rn(fmaxf(acc2[i][j][0] + b0v, 0.f),
                                fmaxf(acc2[i][j][1] + b1v, 0.f));
      *(__nv_bfloat162*)&g_Hs[((size_t)(row + 8) * E_ + bx) * H2_ + col] =
          __floats2bfloat162_rn(fmaxf(acc2[i][j][2] + b0v, 0.f),
                                fmaxf(acc2[i][j][3] + b1v, 0.f));
    }
  }
}

// ---------------- Final: router MLP tail + softmax + expert L3 + mix -----
__global__ __launch_bounds__(256) void k_final(
    const float* __restrict__ rW2, const float* __restrict__ rb2,
    const float* __restrict__ rW3, const float* __restrict__ rb3,
    const float* __restrict__ eW3, const float* __restrict__ eb3,
    float* __restrict__ out) {
  __shared__ float s_rW2[R1_ * R2_];
  __shared__ float s_rW3[R2_ * E_];
  __shared__ float s_eW3[E_ * H2_];
  __shared__ float s_rb2[R2_], s_rb3[E_], s_eb3[E_];
  __shared__ float s_h[8][R1_];
  int tid = threadIdx.x;
  for (int i = tid; i < R1_ * R2_; i += 256) s_rW2[i] = rW2[i];
  for (int i = tid; i < R2_ * E_; i += 256) s_rW3[i] = rW3[i];
  for (int i = tid; i < E_ * H2_; i += 256) s_eW3[i] = eW3[i];
  if (tid < R2_) s_rb2[tid] = rb2[tid];
  if (tid < E_) { s_rb3[tid] = rb3[tid]; s_eb3[tid] = eb3[tid]; }
  __syncthreads();

  int w = tid >> 5, lane = tid & 31;
  int b = blockIdx.x * 8 + w;

  const __nv_bfloat162* hp = (const __nv_bfloat162*)(g_Cr + (size_t)b * R1_);
  __nv_bfloat162 hv = hp[lane];
  s_h[w][2 * lane] = __bfloat162float(hv.x);
  s_h[w][2 * lane + 1] = __bfloat162float(hv.y);
  __syncwarp();

  float d1 = s_rb2[lane];
#pragma unroll
  for (int k = 0; k < R1_; k++) d1 += s_h[w][k] * s_rW2[k * R2_ + lane];
  d1 = fmaxf(d1, 0.f);

  float d2 = (lane < E_) ? s_rb3[lane] : 0.f;
#pragma unroll
  for (int k = 0; k < R2_; k++) {
    float v = __shfl_sync(0xffffffffu, d1, k);
    if (lane < E_) d2 += v * s_rW3[k * E_ + lane];
  }
  float m = d2;
#pragma unroll
  for (int off = 8; off > 0; off >>= 1)
    m = fmaxf(m, __shfl_xor_sync(0xffffffffu, m, off, 16));
  float ex = __expf(d2 - m);
  float s = ex;
#pragma unroll
  for (int off = 8; off > 0; off >>= 1)
    s += __shfl_xor_sync(0xffffffffu, s, off, 16);
  float rw = ex / s;

  float eo = 0.f;
  if (lane < E_) {
    float a2 = s_eb3[lane];
    const __nv_bfloat162* q =
        (const __nv_bfloat162*)(g_Hs + ((size_t)b * E_ + lane) * H2_);
#pragma unroll
    for (int n = 0; n < H2_ / 2; n++) {
      __nv_bfloat162 v = q[n];
      a2 += __bfloat162float(v.x) * s_eW3[lane * H2_ + 2 * n] +
            __bfloat162float(v.y) * s_eW3[lane * H2_ + 2 * n + 1];
    }
    eo = 1.f / (1.f + __expf(-a2));
  }
  float p = rw * eo;
#pragma unroll
  for (int off = 8; off > 0; off >>= 1)
    p += __shfl_xor_sync(0xffffffffu, p, off, 16);

  if (lane < E_) {
    out[(size_t)B_ + (size_t)b * E_ + lane] = rw;
    out[(size_t)B_ + (size_t)B_ * E_ + (size_t)b * E_ + lane] = eo;
  }
  if (lane == 0) out[b] = p;
}

// ---------------- launch ----------------
extern "C" void kernel_launch(void* const* d_in, const int* in_sizes, int n_in,
                              void* d_out, int out_size) {
  const float* x     = (const float*)d_in[0];
  const float* rg    = (const float*)d_in[1];
  const float* rbta  = (const float*)d_in[2];
  const float* rm    = (const float*)d_in[3];
  const float* rv    = (const float*)d_in[4];
  const float* rW1   = (const float*)d_in[5];
  const float* rb1   = (const float*)d_in[6];
  const float* rW2   = (const float*)d_in[7];
  const float* rb2   = (const float*)d_in[8];
  const float* rW3   = (const float*)d_in[9];
  const float* rb3   = (const float*)d_in[10];
  const float* eg    = (const float*)d_in[11];
  const float* ebt   = (const float*)d_in[12];
  const float* em    = (const float*)d_in[13];
  const float* ev    = (const float*)d_in[14];
  const float* eW1   = (const float*)d_in[15];
  const float* eb1   = (const float*)d_in[16];
  const float* eW2   = (const float*)d_in[17];
  const float* eb2   = (const float*)d_in[18];
  const float* eW3   = (const float*)d_in[19];
  const float* eb3   = (const float*)d_in[20];
  float* out = (float*)d_out;

  cudaFuncSetAttribute(k_gemm1f, cudaFuncAttributeMaxDynamicSharedMemorySize,
                       SM_TOT);

  k_cvtx<<<(B_ * D_ / 4) / 256, 256>>>(x);
  k_fold<<<NP, 256>>>(rg, rbta, rm, rv, rW1, rb1, eg, ebt, em, ev, eW1, eb1);
  k_w2t<<<(E_ * H1_ * H2_) / 256, 256>>>(eW2);
  k_gemm1f<<<dim3(E_ + 1, B_ / 128), 256, SM_TOT>>>(eb2);
  k_final<<<B_ / 8, 256>>>(rW2, rb2, rW3, rb3, eW3, eb3, out);
}

// round 4
// speedup vs baseline: 1.7903x; 1.1940x over previous
#include <cuda_runtime.h>
#include <cuda_bf16.h>
#include <stdint.h>
#include <math.h>

// Problem dims
#define B_   65536
#define D_   1024
#define E_   16
#define H1_  128
#define H2_  64
#define R1_  64
#define R2_  32
// Column layout of the big GEMM: [16*128 expert cols][64 router cols][64 pad]
#define NEXP (E_ * H1_)          // 2048
#define NCAT (NEXP + R1_)        // 2112
#define NP   2176
#define EPS  1e-5f

// ---------------- device scratch (no allocs allowed) ----------------
__device__ __nv_bfloat16 g_xb[(size_t)B_ * D_];           // x in bf16
__device__ __nv_bfloat16 g_Wt[(size_t)NP * D_];           // folded W1, [n][k]
__device__ float         g_bcat[NP];                      // folded bias
__device__ __nv_bfloat16 g_Cr[(size_t)B_ * R1_];          // router hidden (relu)
__device__ __nv_bfloat16 g_W2t[(size_t)E_ * H2_ * H1_];   // eW2 transposed [e][h2][h1]
__device__ float         g_Eo[(size_t)E_ * B_];           // expert outputs [e][b]

// ---------------- asm helpers ----------------
__device__ __forceinline__ void mma16816(float c[4],
    uint32_t a0, uint32_t a1, uint32_t a2, uint32_t a3,
    uint32_t b0, uint32_t b1) {
  asm volatile(
    "mma.sync.aligned.m16n8k16.row.col.f32.bf16.bf16.f32 "
    "{%0,%1,%2,%3},{%4,%5,%6,%7},{%8,%9},{%0,%1,%2,%3};"
    : "+f"(c[0]), "+f"(c[1]), "+f"(c[2]), "+f"(c[3])
    : "r"(a0), "r"(a1), "r"(a2), "r"(a3), "r"(b0), "r"(b1));
}

__device__ __forceinline__ void ldsm4(uint32_t& r0, uint32_t& r1,
                                      uint32_t& r2, uint32_t& r3, uint32_t addr) {
  asm volatile("ldmatrix.sync.aligned.m8n8.x4.shared.b16 {%0,%1,%2,%3},[%4];"
               : "=r"(r0), "=r"(r1), "=r"(r2), "=r"(r3) : "r"(addr));
}

__device__ __forceinline__ void cp_async16(uint32_t saddr, const void* gaddr) {
  asm volatile("cp.async.cg.shared.global [%0],[%1],16;" ::"r"(saddr), "l"(gaddr)
               : "memory");
}
__device__ __forceinline__ void cp_commit() {
  asm volatile("cp.async.commit_group;" ::: "memory");
}
__device__ __forceinline__ void cp_wait1() {
  asm volatile("cp.async.wait_group 1;" ::: "memory");
}

__device__ __forceinline__ uint32_t smem_u32(const void* p) {
  uint32_t a;
  asm("{.reg .u64 t; cvta.to.shared.u64 t, %1; cvt.u32.u64 %0, t;}"
      : "=r"(a) : "l"(p));
  return a;
}

// swizzled byte offsets: row of 64 bf16 (128B, 8 chunks) / 128 bf16 (256B, 16)
__device__ __forceinline__ uint32_t swz64(uint32_t row, uint32_t chunk) {
  return row * 128u + ((chunk ^ (row & 7u)) << 4);
}
__device__ __forceinline__ uint32_t swz128(uint32_t row, uint32_t chunk) {
  return row * 256u + ((chunk ^ (row & 7u)) << 4);
}

__device__ __forceinline__ uint32_t pack_relu(float a, float b) {
  __nv_bfloat162 t = __floats2bfloat162_rn(fmaxf(a, 0.f), fmaxf(b, 0.f));
  return *(uint32_t*)&t;
}

// ---------------- P: convert x fp32 -> bf16 ----------------
__global__ __launch_bounds__(256) void k_cvtx(const float* __restrict__ x) {
  size_t i = (size_t)blockIdx.x * 256 + threadIdx.x;
  float4 v = ((const float4*)x)[i];
  __nv_bfloat162* o = (__nv_bfloat162*)g_xb;
  o[2 * i]     = __floats2bfloat162_rn(v.x, v.y);
  o[2 * i + 1] = __floats2bfloat162_rn(v.z, v.w);
}

// ---------------- P: fold BN into W1 (experts first, router, pad) --------
__global__ __launch_bounds__(256) void k_fold(
    const float* __restrict__ rg, const float* __restrict__ rb,
    const float* __restrict__ rm, const float* __restrict__ rv,
    const float* __restrict__ rW1, const float* __restrict__ rb1,
    const float* __restrict__ eg, const float* __restrict__ ebt,
    const float* __restrict__ em, const float* __restrict__ ev,
    const float* __restrict__ eW1, const float* __restrict__ eb1) {
  int n = blockIdx.x;
  int tid = threadIdx.x;
  __shared__ float red[256];
  float acc = 0.f;
  if (n < NEXP) {
    int e = n >> 7, h = n & 127;
    const float* W = eW1 + (size_t)e * D_ * H1_;
    const float* Gg = eg + (size_t)e * D_;
    const float* Gb = ebt + (size_t)e * D_;
    const float* Gm = em + (size_t)e * D_;
    const float* Gv = ev + (size_t)e * D_;
    for (int k = tid; k < D_; k += 256) {
      float sc = Gg[k] * rsqrtf(Gv[k] + EPS);
      float sh = Gb[k] - Gm[k] * sc;
      float wv = W[(size_t)k * H1_ + h];
      g_Wt[(size_t)n * D_ + k] = __float2bfloat16(wv * sc);
      acc += sh * wv;
    }
  } else if (n < NCAT) {
    int rn = n - NEXP;
    for (int k = tid; k < D_; k += 256) {
      float sc = rg[k] * rsqrtf(rv[k] + EPS);
      float sh = rb[k] - rm[k] * sc;
      float wv = rW1[(size_t)k * R1_ + rn];
      g_Wt[(size_t)n * D_ + k] = __float2bfloat16(wv * sc);
      acc += sh * wv;
    }
  } else {
    for (int k = tid; k < D_; k += 256)
      g_Wt[(size_t)n * D_ + k] = __float2bfloat16(0.f);
  }
  red[tid] = acc;
  __syncthreads();
  for (int s = 128; s > 0; s >>= 1) {
    if (tid < s) red[tid] += red[tid + s];
    __syncthreads();
  }
  if (tid == 0) {
    float base = 0.f;
    if (n < NEXP) base = eb1[(size_t)(n >> 7) * H1_ + (n & 127)];
    else if (n < NCAT) base = rb1[n - NEXP];
    g_bcat[n] = base + red[0];
  }
}

// ---------------- P: transpose+convert eW2 -> [e][h2][h1] bf16 ----------
__global__ __launch_bounds__(256) void k_w2t(const float* __restrict__ eW2) {
  int idx = blockIdx.x * 256 + threadIdx.x;  // < 16*128*64
  int e = idx >> 13;
  int r = idx & 8191;
  int k = r >> 6;   // h1
  int n = r & 63;   // h2
  g_W2t[((size_t)e * H2_ + n) * H1_ + k] = __float2bfloat16(eW2[idx]);
}

// ======== Fused GEMM1(+bias+relu) + GEMM2(+bias+relu) + expert L3 ========
// BM=128, BN=128, BK=64, 3-stage cp.async, ldmatrix, 256 thr (2m x 4n warps).
// Smem budget kept < 100KB so 2 CTAs/SM co-reside:
//   A stages: 3 x 16384 @ 0      (H1s reuses A stages 0..1 after mainloop)
//   B stages: 3 x 16384 @ 49152  (W2s @ B0, H2s @ B1 after mainloop)
//   ew3 (64f) @ 98304, eb3 (1f) @ 98560
#define SM_A    0u
#define SM_B    49152u
#define SM_W2   49152u
#define SM_H2   65536u
#define SM_EW3  98304u
#define SM_EB3  98560u
#define SM_TOT  98688u

__global__ __launch_bounds__(256, 2) void k_gemm_f(
    const float* __restrict__ eb2, const float* __restrict__ eW3,
    const float* __restrict__ eb3) {
  extern __shared__ __align__(1024) char smem[];
  const uint32_t sb = smem_u32(smem);
  const int bx = blockIdx.x;            // 0..15 experts, 16 = router(+pad)
  const int m0 = blockIdx.y * 128;
  const int n0 = bx * 128;
  const int tid = threadIdx.x;
  const int wid = tid >> 5, lane = tid & 31;
  const int g = lane >> 2, t = lane & 3;
  const int mW = wid >> 2, nW = wid & 3;
  const int lr = lane & 15, lc = lane >> 4;   // ldmatrix row / chunk add
  float* ew3_s = (float*)(smem + SM_EW3);
  float* eb3_s = (float*)(smem + SM_EB3);

  if (bx < E_) {
    if (tid < H2_) ew3_s[tid] = eW3[bx * H2_ + tid];
    if (tid == 0) eb3_s[0] = eb3[bx];
  }

  float acc[4][4][4];
#pragma unroll
  for (int i = 0; i < 4; i++)
#pragma unroll
    for (int j = 0; j < 4; j++)
#pragma unroll
      for (int c = 0; c < 4; c++) acc[i][j][c] = 0.f;

  auto load_stage = [&](int st, int k0) {
#pragma unroll
    for (int i = 0; i < 2; i++) {
      int idx = tid + 256 * i;          // 0..511 of 1024 per operand
      int row = idx >> 3, ch = idx & 7;
      uint32_t so = swz64(row, ch);
      cp_async16(sb + SM_A + st * 16384u + so,
                 g_xb + (size_t)(m0 + row) * D_ + k0 + ch * 8);
      cp_async16(sb + SM_B + st * 16384u + so,
                 g_Wt + (size_t)(n0 + row) * D_ + k0 + ch * 8);
    }
#pragma unroll
    for (int i = 2; i < 4; i++) {
      int idx = tid + 256 * i;
      int row = idx >> 3, ch = idx & 7;
      uint32_t so = swz64(row, ch);
      cp_async16(sb + SM_A + st * 16384u + so,
                 g_xb + (size_t)(m0 + row) * D_ + k0 + ch * 8);
      cp_async16(sb + SM_B + st * 16384u + so,
                 g_Wt + (size_t)(n0 + row) * D_ + k0 + ch * 8);
    }
  };

  load_stage(0, 0);  cp_commit();
  load_stage(1, 64); cp_commit();

  const int NITER = D_ / 64;  // 16
  for (int it = 0; it < NITER; ++it) {
    cp_wait1();
    __syncthreads();
    if (it + 2 < NITER) load_stage((it + 2) % 3, (it + 2) * 64);
    cp_commit();
    const uint32_t sAb = sb + SM_A + (uint32_t)(it % 3) * 16384u;
    const uint32_t sBb = sb + SM_B + (uint32_t)(it % 3) * 16384u;
#pragma unroll
    for (int kk = 0; kk < 4; ++kk) {
      uint32_t a[4][4], bfr[2][4];
#pragma unroll
      for (int i = 0; i < 4; i++)
        ldsm4(a[i][0], a[i][1], a[i][2], a[i][3],
              sAb + swz64(mW * 64 + i * 16 + lr, 2 * kk + lc));
#pragma unroll
      for (int jj = 0; jj < 2; jj++)
        ldsm4(bfr[jj][0], bfr[jj][1], bfr[jj][2], bfr[jj][3],
              sBb + swz64(nW * 32 + jj * 16 + lr, 2 * kk + lc));
#pragma unroll
      for (int i = 0; i < 4; i++)
#pragma unroll
        for (int j = 0; j < 4; j++)
          mma16816(acc[i][j], a[i][0], a[i][1], a[i][2], a[i][3],
                   bfr[j >> 1][j & 1], bfr[j >> 1][(j & 1) + 2]);
    }
  }
  __syncthreads();   // mainloop smem now dead

  if (bx < E_) {
    // ---- h1 = relu(acc+bias) -> H1s (A-stage region), swz128 ----
#pragma unroll
    for (int i = 0; i < 4; i++) {
#pragma unroll
      for (int j = 0; j < 4; j++) {
        int row = mW * 64 + i * 16 + g;
        int col = nW * 32 + j * 8 + 2 * t;
        float b0v = g_bcat[n0 + col], b1v = g_bcat[n0 + col + 1];
        *(uint32_t*)(smem + SM_A + swz128(row, col >> 3) + (col & 7) * 2) =
            pack_relu(acc[i][j][0] + b0v, acc[i][j][1] + b1v);
        *(uint32_t*)(smem + SM_A + swz128(row + 8, col >> 3) + (col & 7) * 2) =
            pack_relu(acc[i][j][2] + b0v, acc[i][j][3] + b1v);
      }
    }
    // ---- stage W2[e] (64x128 bf16) -> W2s (B0), swz128 ----
#pragma unroll
    for (int i = 0; i < 4; i++) {
      int idx = tid + 256 * i;          // 64 rows x 16 chunks
      int row = idx >> 4, ch = idx & 15;
      uint4 v = *(const uint4*)(g_W2t + ((size_t)bx * H2_ + row) * H1_ + ch * 8);
      *(uint4*)(smem + SM_W2 + swz128(row, ch)) = v;
    }
    __syncthreads();

    // ---- GEMM2: h2 = relu(H1s @ W2s^T + eb2[e]) -> H2s; m128 n64 K=128 ----
    float acc2[4][2][4];
#pragma unroll
    for (int i = 0; i < 4; i++)
#pragma unroll
      for (int j = 0; j < 2; j++)
#pragma unroll
        for (int c = 0; c < 4; c++) acc2[i][j][c] = 0.f;

#pragma unroll
    for (int ks = 0; ks < 8; ++ks) {
      uint32_t a[4][4], bfr[4];
#pragma unroll
      for (int i = 0; i < 4; i++)
        ldsm4(a[i][0], a[i][1], a[i][2], a[i][3],
              sb + SM_A + swz128(mW * 64 + i * 16 + lr, 2 * ks + lc));
      ldsm4(bfr[0], bfr[1], bfr[2], bfr[3],
            sb + SM_W2 + swz128(nW * 16 + lr, 2 * ks + lc));
#pragma unroll
      for (int i = 0; i < 4; i++) {
        mma16816(acc2[i][0], a[i][0], a[i][1], a[i][2], a[i][3], bfr[0], bfr[2]);
        mma16816(acc2[i][1], a[i][0], a[i][1], a[i][2], a[i][3], bfr[1], bfr[3]);
      }
    }
#pragma unroll
    for (int i = 0; i < 4; i++) {
#pragma unroll
      for (int j = 0; j < 2; j++) {
        int row = mW * 64 + i * 16 + g;
        int col = nW * 16 + j * 8 + 2 * t;
        float b0v = eb2[bx * H2_ + col], b1v = eb2[bx * H2_ + col + 1];
        *(uint32_t*)(smem + SM_H2 + swz64(row, col >> 3) + (col & 7) * 2) =
            pack_relu(acc2[i][j][0] + b0v, acc2[i][j][1] + b1v);
        *(uint32_t*)(smem + SM_H2 + swz64(row + 8, col >> 3) + (col & 7) * 2) =
            pack_relu(acc2[i][j][2] + b0v, acc2[i][j][3] + b1v);
      }
    }
    __syncthreads();

    // ---- expert L3: per-row dot64 + sigmoid -> g_Eo[e][b] ----
    if (tid < 128) {
      float logit = eb3_s[0];
#pragma unroll
      for (int ch = 0; ch < 8; ch++) {
        uint4 v = *(const uint4*)(smem + SM_H2 + swz64(tid, ch));
        const __nv_bfloat162* p = (const __nv_bfloat162*)&v;
#pragma unroll
        for (int q = 0; q < 4; q++) {
          float2 f = __bfloat1622float2(p[q]);
          logit += f.x * ew3_s[ch * 8 + 2 * q] + f.y * ew3_s[ch * 8 + 2 * q + 1];
        }
      }
      g_Eo[(size_t)bx * B_ + m0 + tid] = 1.f / (1.f + __expf(-logit));
    }
  } else {
    // ---- router block: cols [0,64) -> relu -> g_Cr ----
    if (nW < 2) {
#pragma unroll
      for (int i = 0; i < 4; i++) {
#pragma unroll
        for (int j = 0; j < 4; j++) {
          int row = m0 + mW * 64 + i * 16 + g;
          int col = nW * 32 + j * 8 + 2 * t;
          float b0v = g_bcat[NEXP + col], b1v = g_bcat[NEXP + col + 1];
          *(uint32_t*)&g_Cr[(size_t)row * R1_ + col] =
              pack_relu(acc[i][j][0] + b0v, acc[i][j][1] + b1v);
          *(uint32_t*)&g_Cr[(size_t)(row + 8) * R1_ + col] =
              pack_relu(acc[i][j][2] + b0v, acc[i][j][3] + b1v);
        }
      }
    }
  }
}

// ---------------- Final: router MLP tail + softmax + mix -----------------
__global__ __launch_bounds__(256) void k_final(
    const float* __restrict__ rW2, const float* __restrict__ rb2,
    const float* __restrict__ rW3, const float* __restrict__ rb3,
    float* __restrict__ out) {
  __shared__ float s_rW2[R1_ * R2_];
  __shared__ float s_rW3[R2_ * E_];
  __shared__ float s_rb2[R2_], s_rb3[E_];
  __shared__ float s_h[8][R1_];
  int tid = threadIdx.x;
  for (int i = tid; i < R1_ * R2_; i += 256) s_rW2[i] = rW2[i];
  for (int i = tid; i < R2_ * E_; i += 256) s_rW3[i] = rW3[i];
  if (tid < R2_) s_rb2[tid] = rb2[tid];
  if (tid < E_) s_rb3[tid] = rb3[tid];
  __syncthreads();

  int w = tid >> 5, lane = tid & 31;
  int b = blockIdx.x * 8 + w;

  const __nv_bfloat162* hp = (const __nv_bfloat162*)(g_Cr + (size_t)b * R1_);
  __nv_bfloat162 hv = hp[lane];
  s_h[w][2 * lane] = __bfloat162float(hv.x);
  s_h[w][2 * lane + 1] = __bfloat162float(hv.y);
  __syncwarp();

  float d1 = s_rb2[lane];
#pragma unroll
  for (int k = 0; k < R1_; k++) d1 += s_h[w][k] * s_rW2[k * R2_ + lane];
  d1 = fmaxf(d1, 0.f);

  float d2 = (lane < E_) ? s_rb3[lane] : 0.f;
#pragma unroll
  for (int k = 0; k < R2_; k++) {
    float v = __shfl_sync(0xffffffffu, d1, k);
    if (lane < E_) d2 += v * s_rW3[k * E_ + lane];
  }
  float m = d2;
#pragma unroll
  for (int off = 8; off > 0; off >>= 1)
    m = fmaxf(m, __shfl_xor_sync(0xffffffffu, m, off, 16));
  float ex = __expf(d2 - m);
  float s = ex;
#pragma unroll
  for (int off = 8; off > 0; off >>= 1)
    s += __shfl_xor_sync(0xffffffffu, s, off, 16);
  float rw = ex / s;

  float eo = (lane < E_) ? g_Eo[(size_t)lane * B_ + b] : 0.f;
  float p = rw * eo;
#pragma unroll
  for (int off = 8; off > 0; off >>= 1)
    p += __shfl_xor_sync(0xffffffffu, p, off, 16);

  if (lane < E_) {
    out[(size_t)B_ + (size_t)b * E_ + lane] = rw;
    out[(size_t)B_ + (size_t)B_ * E_ + (size_t)b * E_ + lane] = eo;
  }
  if (lane == 0) out[b] = p;
}

// ---------------- launch ----------------
extern "C" void kernel_launch(void* const* d_in, const int* in_sizes, int n_in,
                              void* d_out, int out_size) {
  const float* x     = (const float*)d_in[0];
  const float* rg    = (const float*)d_in[1];
  const float* rbta  = (const float*)d_in[2];
  const float* rm    = (const float*)d_in[3];
  const float* rv    = (const float*)d_in[4];
  const float* rW1   = (const float*)d_in[5];
  const float* rb1   = (const float*)d_in[6];
  const float* rW2   = (const float*)d_in[7];
  const float* rb2   = (const float*)d_in[8];
  const float* rW3   = (const float*)d_in[9];
  const float* rb3   = (const float*)d_in[10];
  const float* eg    = (const float*)d_in[11];
  const float* ebt   = (const float*)d_in[12];
  const float* em    = (const float*)d_in[13];
  const float* ev    = (const float*)d_in[14];
  const float* eW1   = (const float*)d_in[15];
  const float* eb1   = (const float*)d_in[16];
  const float* eW2   = (const float*)d_in[17];
  const float* eb2   = (const float*)d_in[18];
  const float* eW3   = (const float*)d_in[19];
  const float* eb3   = (const float*)d_in[20];
  float* out = (float*)d_out;

  cudaFuncSetAttribute(k_gemm_f, cudaFuncAttributeMaxDynamicSharedMemorySize,
                       SM_TOT);

  k_cvtx<<<(B_ * D_ / 4) / 256, 256>>>(x);
  k_fold<<<NP, 256>>>(rg, rbta, rm, rv, rW1, rb1, eg, ebt, em, ev, eW1, eb1);
  k_w2t<<<(E_ * H1_ * H2_) / 256, 256>>>(eW2);
  k_gemm_f<<<dim3(E_ + 1, B_ / 128), 256, SM_TOT>>>(eb2, eW3, eb3);
  k_final<<<B_ / 8, 256>>>(rW2, rb2, rW3, rb3, out);
}